// round 1
// baseline (speedup 1.0000x reference)
#include <cuda_runtime.h>
#include <math.h>

// Problem constants (shapes fixed by setup_inputs; recursive_index=0 -> G=8)
#define BB 8
#define NN 4096
#define CC 512
#define GG 8
#define HH 8
#define DH 64
#define LL 512          // tokens per group = NN/GG

// Scratch (device globals; no cudaMalloc allowed)
__device__ float g_qkv[(size_t)BB * NN * 3 * CC];   // [32768, 1536]
__device__ float g_att[(size_t)BB * NN * CC];       // [32768, 512]

// ---------------------------------------------------------------------------
// Generic tiled SGEMM: C[M,N] = A[M,K] @ B[K,N] (+ bias), all row-major fp32.
// BM=128, BN=64, BK=16, 256 threads, 8x4 per-thread tile.
// ---------------------------------------------------------------------------
__global__ __launch_bounds__(256) void sgemm_kernel(
    const float* __restrict__ A, const float* __restrict__ Bm,
    const float* __restrict__ bias, float* __restrict__ C,
    int M, int N, int K)
{
    constexpr int BM = 128, BN = 64, BK = 16, TM = 8, TN = 4;
    __shared__ float As[BK][BM];   // transposed: As[k][m]
    __shared__ float Bs[BK][BN];   // Bs[k][n]

    const int tid = threadIdx.x;
    const int tx = tid & 15;       // 16 col groups
    const int ty = tid >> 4;       // 16 row groups
    const int m0 = blockIdx.y * BM;
    const int n0 = blockIdx.x * BN;

    float acc[TM][TN];
    #pragma unroll
    for (int i = 0; i < TM; i++)
        #pragma unroll
        for (int j = 0; j < TN; j++) acc[i][j] = 0.f;

    for (int k0 = 0; k0 < K; k0 += BK) {
        // Load A tile: 128x16 floats = 512 float4, 2 per thread
        #pragma unroll
        for (int it = 0; it < 2; ++it) {
            int s = tid + 256 * it;          // 0..511
            int r = s >> 2, kq = s & 3;
            float4 v = *(const float4*)&A[(size_t)(m0 + r) * K + k0 + kq * 4];
            As[kq * 4 + 0][r] = v.x;
            As[kq * 4 + 1][r] = v.y;
            As[kq * 4 + 2][r] = v.z;
            As[kq * 4 + 3][r] = v.w;
        }
        // Load B tile: 16x64 floats = 256 float4, 1 per thread
        {
            int kr = tid >> 4, nq = tid & 15;
            *(float4*)&Bs[kr][nq * 4] =
                *(const float4*)&Bm[(size_t)(k0 + kr) * N + n0 + nq * 4];
        }
        __syncthreads();

        #pragma unroll
        for (int kk = 0; kk < BK; ++kk) {
            float a[TM], b[TN];
            float4 a0 = *(const float4*)&As[kk][ty * TM];
            float4 a1 = *(const float4*)&As[kk][ty * TM + 4];
            a[0]=a0.x; a[1]=a0.y; a[2]=a0.z; a[3]=a0.w;
            a[4]=a1.x; a[5]=a1.y; a[6]=a1.z; a[7]=a1.w;
            float4 b0 = *(const float4*)&Bs[kk][tx * TN];
            b[0]=b0.x; b[1]=b0.y; b[2]=b0.z; b[3]=b0.w;
            #pragma unroll
            for (int i = 0; i < TM; i++)
                #pragma unroll
                for (int j = 0; j < TN; j++)
                    acc[i][j] = fmaf(a[i], b[j], acc[i][j]);
        }
        __syncthreads();
    }

    // Epilogue
    float bj[TN];
    #pragma unroll
    for (int j = 0; j < TN; j++) bj[j] = bias ? bias[n0 + tx * TN + j] : 0.f;
    #pragma unroll
    for (int i = 0; i < TM; i++) {
        float4 v;
        v.x = acc[i][0] + bj[0];
        v.y = acc[i][1] + bj[1];
        v.z = acc[i][2] + bj[2];
        v.w = acc[i][3] + bj[3];
        *(float4*)&C[(size_t)(m0 + ty * TM + i) * N + n0 + tx * TN] = v;
    }
}

// ---------------------------------------------------------------------------
// Fused flash-style grouped attention (fp32).
// Grid: (8 row-chunks, B*G*H = 512). Block: 256 threads.
// Each CTA: 64 query rows of one (b,g,h) block; loops over 8 kv chunks of 64.
// Dynamic smem: Qs[64][64] d-major, Ks[64][64] d-major, Vs[64][64], Ps[64][64].
// ---------------------------------------------------------------------------
__global__ __launch_bounds__(256) void attn_kernel()
{
    extern __shared__ float sm[];
    float* Qs = sm;                 // Qs[d*64 + i]
    float* Ks = sm + 64 * 64;       // Ks[d*64 + m]
    float* Vs = sm + 2 * 64 * 64;   // Vs[m*64 + d]
    float* Ps = sm + 3 * 64 * 64;   // Ps[i*64 + m]

    const int tid = threadIdx.x;
    const int tx = tid & 15;
    const int ty = tid >> 4;
    const int bgh = blockIdx.y;
    const int h = bgh & 7;
    const int g = (bgh >> 3) & 7;
    const int b = bgh >> 6;
    const int t0 = b * NN + g * LL;            // token base of this group
    const int qrow0 = blockIdx.x * 64;
    const float scale = 0.125f;                // 64^-0.5

    // Load Q chunk, transposed to d-major
    #pragma unroll
    for (int it = 0; it < 4; ++it) {
        int s = tid + 256 * it;                // 0..1023 float4 slots
        int r = s >> 4, dq = s & 15;
        float4 v = *(const float4*)&g_qkv[(size_t)(t0 + qrow0 + r) * 1536 + h * 64 + dq * 4];
        Qs[(dq * 4 + 0) * 64 + r] = v.x;
        Qs[(dq * 4 + 1) * 64 + r] = v.y;
        Qs[(dq * 4 + 2) * 64 + r] = v.z;
        Qs[(dq * 4 + 3) * 64 + r] = v.w;
    }

    float acc[4][4];
    float rmax[4], rsum[4];
    #pragma unroll
    for (int i = 0; i < 4; i++) {
        rmax[i] = -1e30f; rsum[i] = 0.f;
        #pragma unroll
        for (int j = 0; j < 4; j++) acc[i][j] = 0.f;
    }

    for (int c = 0; c < 8; ++c) {
        // Load K chunk (transposed) and V chunk
        #pragma unroll
        for (int it = 0; it < 4; ++it) {
            int s = tid + 256 * it;
            int r = s >> 4, dq = s & 15;
            const float* kp = &g_qkv[(size_t)(t0 + c * 64 + r) * 1536 + 512 + h * 64 + dq * 4];
            float4 v = *(const float4*)kp;
            Ks[(dq * 4 + 0) * 64 + r] = v.x;
            Ks[(dq * 4 + 1) * 64 + r] = v.y;
            Ks[(dq * 4 + 2) * 64 + r] = v.z;
            Ks[(dq * 4 + 3) * 64 + r] = v.w;
            float4 w = *(const float4*)(kp + 512);   // v offset = 1024 = 512+512
            *(float4*)&Vs[r * 64 + dq * 4] = w;
        }
        __syncthreads();

        // S = scale * (Q K^T) -- 64x64x64 register-tiled GEMM
        float s_[4][4];
        #pragma unroll
        for (int i = 0; i < 4; i++)
            #pragma unroll
            for (int j = 0; j < 4; j++) s_[i][j] = 0.f;

        #pragma unroll 8
        for (int d = 0; d < 64; ++d) {
            float4 av = *(const float4*)&Qs[d * 64 + ty * 4];
            float4 bv = *(const float4*)&Ks[d * 64 + tx * 4];
            float a[4] = {av.x, av.y, av.z, av.w};
            float bb[4] = {bv.x, bv.y, bv.z, bv.w};
            #pragma unroll
            for (int i = 0; i < 4; i++)
                #pragma unroll
                for (int j = 0; j < 4; j++)
                    s_[i][j] = fmaf(a[i], bb[j], s_[i][j]);
        }

        // Online softmax (row stats replicated across the 16 tx lanes)
        float nm[4], alpha[4], csum[4];
        #pragma unroll
        for (int i = 0; i < 4; i++) {
            float cm = -1e30f;
            #pragma unroll
            for (int j = 0; j < 4; j++) {
                s_[i][j] *= scale;
                cm = fmaxf(cm, s_[i][j]);
            }
            #pragma unroll
            for (int off = 8; off; off >>= 1)
                cm = fmaxf(cm, __shfl_xor_sync(0xffffffffu, cm, off));
            nm[i] = fmaxf(rmax[i], cm);
            alpha[i] = __expf(rmax[i] - nm[i]);
            float cs = 0.f;
            #pragma unroll
            for (int j = 0; j < 4; j++) {
                s_[i][j] = __expf(s_[i][j] - nm[i]);
                cs += s_[i][j];
            }
            #pragma unroll
            for (int off = 8; off; off >>= 1)
                cs += __shfl_xor_sync(0xffffffffu, cs, off);
            csum[i] = cs;
            rsum[i] = rsum[i] * alpha[i] + csum[i];
            rmax[i] = nm[i];
            #pragma unroll
            for (int j = 0; j < 4; j++) acc[i][j] *= alpha[i];
        }

        // Stash P to smem (separate buffer; safe without extra barrier)
        #pragma unroll
        for (int i = 0; i < 4; i++)
            *(float4*)&Ps[(ty * 4 + i) * 64 + tx * 4] =
                make_float4(s_[i][0], s_[i][1], s_[i][2], s_[i][3]);
        __syncthreads();

        // O += P @ V -- 64x64x64 register-tiled GEMM
        #pragma unroll 8
        for (int m = 0; m < 64; ++m) {
            float a[4], bb[4];
            #pragma unroll
            for (int i = 0; i < 4; i++) a[i] = Ps[(ty * 4 + i) * 64 + m];
            float4 bv = *(const float4*)&Vs[m * 64 + tx * 4];
            bb[0]=bv.x; bb[1]=bv.y; bb[2]=bv.z; bb[3]=bv.w;
            #pragma unroll
            for (int i = 0; i < 4; i++)
                #pragma unroll
                for (int j = 0; j < 4; j++)
                    acc[i][j] = fmaf(a[i], bb[j], acc[i][j]);
        }
        __syncthreads();   // before next chunk overwrites Ks/Vs
    }

    // Normalize and write to g_att in [B, Np, C] layout (col = h*64 + d)
    #pragma unroll
    for (int i = 0; i < 4; i++) {
        float inv = 1.f / rsum[i];
        float4 v = make_float4(acc[i][0] * inv, acc[i][1] * inv,
                               acc[i][2] * inv, acc[i][3] * inv);
        *(float4*)&g_att[(size_t)(t0 + qrow0 + ty * 4 + i) * CC + h * 64 + tx * 4] = v;
    }
}

// ---------------------------------------------------------------------------
extern "C" void kernel_launch(void* const* d_in, const int* in_sizes, int n_in,
                              void* d_out, int out_size)
{
    const float* x      = (const float*)d_in[0];   // [8,4096,512]
    const float* W_qkv  = (const float*)d_in[1];   // [512,1536]
    const float* W_proj = (const float*)d_in[2];   // [512,512]
    const float* b_proj = (const float*)d_in[3];   // [512]
    float* out = (float*)d_out;                    // [8,4096,512]

    float* qkv_ptr = nullptr;
    float* att_ptr = nullptr;
    cudaGetSymbolAddress((void**)&qkv_ptr, g_qkv);
    cudaGetSymbolAddress((void**)&att_ptr, g_att);

    const int M = BB * NN;   // 32768

    // 1) qkv = x @ W_qkv   [32768,512]x[512,1536]
    {
        dim3 grid((3 * CC) / 64, M / 128);
        sgemm_kernel<<<grid, 256>>>(x, W_qkv, nullptr, qkv_ptr, M, 3 * CC, CC);
    }

    // 2) fused grouped attention -> g_att
    {
        static int smem_set = 0;
        if (!smem_set) {
            cudaFuncSetAttribute(attn_kernel,
                                 cudaFuncAttributeMaxDynamicSharedMemorySize,
                                 4 * 64 * 64 * (int)sizeof(float));
            smem_set = 1;
        }
        dim3 grid(LL / 64, BB * GG * HH);   // (8, 512)
        attn_kernel<<<grid, 256, 4 * 64 * 64 * sizeof(float)>>>();
    }

    // 3) out = g_att @ W_proj + b_proj   [32768,512]x[512,512]
    {
        dim3 grid(CC / 64, M / 128);
        sgemm_kernel<<<grid, 256>>>(att_ptr, W_proj, b_proj, out, M, CC, CC);
    }
}

// round 3
// speedup vs baseline: 1.4556x; 1.4556x over previous
#include <cuda_runtime.h>
#include <cuda_bf16.h>
#include <math.h>
#include <stdint.h>

// Problem constants (recursive_index=0 -> G=8)
#define BB 8
#define NN 4096
#define CC 512
#define GG 8
#define HH 8
#define DH 64
#define LL 512

// Scratch (device globals; no cudaMalloc allowed)
__device__ float g_qkv[(size_t)BB * NN * 3 * CC];            // [32768, 1536] fp32
__device__ float g_att[(size_t)BB * NN * CC];                // [32768, 512]  fp32
__device__ __nv_bfloat16 g_wq_hi[(size_t)CC * 3 * CC];       // [512, 1536] (K,N)
__device__ __nv_bfloat16 g_wq_lo[(size_t)CC * 3 * CC];
__device__ __nv_bfloat16 g_wp_hi[(size_t)CC * CC];           // [512, 512]
__device__ __nv_bfloat16 g_wp_lo[(size_t)CC * CC];

// ---------------------------------------------------------------------------
// Helpers
// ---------------------------------------------------------------------------
__device__ __forceinline__ uint32_t smem_u32(const void* p) {
    uint32_t a;
    asm("{ .reg .u64 t; cvta.to.shared.u64 t, %1; cvt.u32.u64 %0, t; }" : "=r"(a) : "l"(p));
    return a;
}

#define LDM_X4(r, a) \
    asm volatile("ldmatrix.sync.aligned.m8n8.x4.shared.b16 {%0,%1,%2,%3}, [%4];" \
        : "=r"((r)[0]), "=r"((r)[1]), "=r"((r)[2]), "=r"((r)[3]) : "r"(a))

#define LDM_X4T(r, a) \
    asm volatile("ldmatrix.sync.aligned.m8n8.x4.trans.shared.b16 {%0,%1,%2,%3}, [%4];" \
        : "=r"((r)[0]), "=r"((r)[1]), "=r"((r)[2]), "=r"((r)[3]) : "r"(a))

#define MMA16816(c, a, b0, b1) \
    asm volatile("mma.sync.aligned.m16n8k16.row.col.f32.bf16.bf16.f32 " \
        "{%0,%1,%2,%3}, {%4,%5,%6,%7}, {%8,%9}, {%0,%1,%2,%3};" \
        : "+f"((c)[0]), "+f"((c)[1]), "+f"((c)[2]), "+f"((c)[3]) \
        : "r"((a)[0]), "r"((a)[1]), "r"((a)[2]), "r"((a)[3]), "r"(b0), "r"(b1))

__device__ __forceinline__ uint32_t pk(__nv_bfloat162 v) {
    return *reinterpret_cast<uint32_t*>(&v);
}

// ---------------------------------------------------------------------------
// Split weights: W [K, N] fp32 -> hi/lo [K, N] bf16 (same layout)
// ---------------------------------------------------------------------------
__global__ void splitw_kernel(const float* __restrict__ W,
                              __nv_bfloat16* __restrict__ hi,
                              __nv_bfloat16* __restrict__ lo, int total) {
    int idx = blockIdx.x * blockDim.x + threadIdx.x;
    if (idx >= total) return;
    float v = W[idx];
    __nv_bfloat16 h = __float2bfloat16_rn(v);
    hi[idx] = h;
    lo[idx] = __float2bfloat16_rn(v - __bfloat162float(h));
}

// ---------------------------------------------------------------------------
// HMMA bf16x3 GEMM: C[M,N] = A[M,K](fp32) @ B[K,N](bf16 hi/lo) (+bias)
// CTA 128x128, 8 warps (2x4 of 64x32), K-chunk 64.
// Smem: Ah/Al [128][72] bf16 (m-major), Bh/Bl [64][136] bf16 (k-major).
// ---------------------------------------------------------------------------
#define SA 72
#define SB 136
#define SM_AH 0
#define SM_AL (128 * SA * 2)
#define SM_BH (2 * 128 * SA * 2)
#define SM_BL (2 * 128 * SA * 2 + 64 * SB * 2)
#define GSM_TOTAL (2 * 128 * SA * 2 + 2 * 64 * SB * 2)   // 71680

__global__ __launch_bounds__(256) void gemm_mma_kernel(
    const float* __restrict__ A, const __nv_bfloat16* __restrict__ Bhi,
    const __nv_bfloat16* __restrict__ Blo, const float* __restrict__ bias,
    float* __restrict__ C, int M, int N, int K)
{
    extern __shared__ char sm[];
    const uint32_t sb = smem_u32(sm);
    __nv_bfloat16* Ah = (__nv_bfloat16*)(sm + SM_AH);
    __nv_bfloat16* Al = (__nv_bfloat16*)(sm + SM_AL);
    __nv_bfloat16* Bh = (__nv_bfloat16*)(sm + SM_BH);
    __nv_bfloat16* Bl = (__nv_bfloat16*)(sm + SM_BL);

    const int tid = threadIdx.x;
    const int wid = tid >> 5, lane = tid & 31;
    const int wm = wid >> 2, wn = wid & 3;        // warp tile: 64(M) x 32(N)
    const int gid = lane >> 2, tig = lane & 3;
    const int m0 = blockIdx.y * 128, n0 = blockIdx.x * 128;

    // ldmatrix lane-address components
    const int a_row = lane & 15;                  // A: row within 16
    const int a_col = (lane >> 4) * 8;            // A: k-col 0/8
    const int b_krow = (lane & 7) + ((lane & 8) ? 8 : 0);   // B: k within 16
    const int b_ncol = (lane & 16) ? 8 : 0;                  // B: n 0/8

    float acc[4][4][4];
    #pragma unroll
    for (int i = 0; i < 4; i++)
        #pragma unroll
        for (int j = 0; j < 4; j++)
            #pragma unroll
            for (int t = 0; t < 4; t++) acc[i][j][t] = 0.f;

    const int NC = K >> 6;
    for (int c = 0; c < NC; ++c) {
        if (c) __syncthreads();
        // --- load A chunk: 128x64 fp32, split to bf16 hi/lo ---
        #pragma unroll
        for (int i = 0; i < 8; ++i) {
            int s = tid + 256 * i;        // 0..2047
            int r = s >> 4, q = s & 15;
            float4 v = *(const float4*)&A[(size_t)(m0 + r) * K + c * 64 + q * 4];
            __nv_bfloat162 h01 = __floats2bfloat162_rn(v.x, v.y);
            __nv_bfloat162 h23 = __floats2bfloat162_rn(v.z, v.w);
            __nv_bfloat162 l01 = __floats2bfloat162_rn(v.x - __bfloat162float(h01.x),
                                                       v.y - __bfloat162float(h01.y));
            __nv_bfloat162 l23 = __floats2bfloat162_rn(v.z - __bfloat162float(h23.x),
                                                       v.w - __bfloat162float(h23.y));
            int off = r * SA + q * 4;
            uint2 hh; hh.x = pk(h01); hh.y = pk(h23);
            uint2 ll; ll.x = pk(l01); ll.y = pk(l23);
            *(uint2*)(Ah + off) = hh;
            *(uint2*)(Al + off) = ll;
        }
        // --- load B chunk: 64x128 bf16 hi+lo ---
        #pragma unroll
        for (int i = 0; i < 4; ++i) {
            int s = tid + 256 * i;        // 0..1023
            int kr = s >> 4, nq = s & 15;
            size_t g = (size_t)(c * 64 + kr) * N + n0 + nq * 8;
            uint4 vh = *(const uint4*)(Bhi + g);
            uint4 vl = *(const uint4*)(Blo + g);
            int off = kr * SB + nq * 8;
            *(uint4*)(Bh + off) = vh;
            *(uint4*)(Bl + off) = vl;
        }
        __syncthreads();

        // --- compute: 4 k16 steps ---
        #pragma unroll
        for (int ks = 0; ks < 4; ++ks) {
            uint32_t bh[2][4], bl[2][4], af[4][4];
            #pragma unroll
            for (int p = 0; p < 2; ++p) {
                int krow = ks * 16 + b_krow;
                int ncol = wn * 32 + p * 16 + b_ncol;
                LDM_X4T(bh[p], sb + SM_BH + (uint32_t)(krow * SB + ncol) * 2);
                LDM_X4T(bl[p], sb + SM_BL + (uint32_t)(krow * SB + ncol) * 2);
            }
            #pragma unroll
            for (int i = 0; i < 4; ++i) {
                int mr = wm * 64 + i * 16 + a_row;
                LDM_X4(af[i], sb + SM_AH + (uint32_t)(mr * SA + ks * 16 + a_col) * 2);
            }
            #pragma unroll
            for (int i = 0; i < 4; ++i)
                #pragma unroll
                for (int j = 0; j < 4; ++j) {
                    int p = j >> 1, q2 = (j & 1) * 2;
                    MMA16816(acc[i][j], af[i], bh[p][q2], bh[p][q2 + 1]);
                    MMA16816(acc[i][j], af[i], bl[p][q2], bl[p][q2 + 1]);
                }
            #pragma unroll
            for (int i = 0; i < 4; ++i) {
                int mr = wm * 64 + i * 16 + a_row;
                LDM_X4(af[i], sb + SM_AL + (uint32_t)(mr * SA + ks * 16 + a_col) * 2);
            }
            #pragma unroll
            for (int i = 0; i < 4; ++i)
                #pragma unroll
                for (int j = 0; j < 4; ++j) {
                    int p = j >> 1, q2 = (j & 1) * 2;
                    MMA16816(acc[i][j], af[i], bh[p][q2], bh[p][q2 + 1]);
                }
        }
    }

    // --- epilogue ---
    #pragma unroll
    for (int i = 0; i < 4; ++i) {
        int r0 = m0 + wm * 64 + i * 16 + gid;
        #pragma unroll
        for (int j = 0; j < 4; ++j) {
            int cc = n0 + wn * 32 + j * 8 + 2 * tig;
            float bx = 0.f, by = 0.f;
            if (bias) { bx = bias[cc]; by = bias[cc + 1]; }
            float2 v0 = make_float2(acc[i][j][0] + bx, acc[i][j][1] + by);
            float2 v1 = make_float2(acc[i][j][2] + bx, acc[i][j][3] + by);
            *(float2*)&C[(size_t)r0 * N + cc] = v0;
            *(float2*)&C[(size_t)(r0 + 8) * N + cc] = v1;
        }
    }
}

// ---------------------------------------------------------------------------
// Fused flash-style grouped attention (fp32) — unchanged (validated R1)
// ---------------------------------------------------------------------------
__global__ __launch_bounds__(256) void attn_kernel()
{
    extern __shared__ float smf[];
    float* Qs = smf;
    float* Ks = smf + 64 * 64;
    float* Vs = smf + 2 * 64 * 64;
    float* Ps = smf + 3 * 64 * 64;

    const int tid = threadIdx.x;
    const int tx = tid & 15;
    const int ty = tid >> 4;
    const int bgh = blockIdx.y;
    const int h = bgh & 7;
    const int g = (bgh >> 3) & 7;
    const int b = bgh >> 6;
    const int t0 = b * NN + g * LL;
    const int qrow0 = blockIdx.x * 64;
    const float scale = 0.125f;

    #pragma unroll
    for (int it = 0; it < 4; ++it) {
        int s = tid + 256 * it;
        int r = s >> 4, dq = s & 15;
        float4 v = *(const float4*)&g_qkv[(size_t)(t0 + qrow0 + r) * 1536 + h * 64 + dq * 4];
        Qs[(dq * 4 + 0) * 64 + r] = v.x;
        Qs[(dq * 4 + 1) * 64 + r] = v.y;
        Qs[(dq * 4 + 2) * 64 + r] = v.z;
        Qs[(dq * 4 + 3) * 64 + r] = v.w;
    }

    float acc[4][4];
    float rmax[4], rsum[4];
    #pragma unroll
    for (int i = 0; i < 4; i++) {
        rmax[i] = -1e30f; rsum[i] = 0.f;
        #pragma unroll
        for (int j = 0; j < 4; j++) acc[i][j] = 0.f;
    }

    for (int c = 0; c < 8; ++c) {
        #pragma unroll
        for (int it = 0; it < 4; ++it) {
            int s = tid + 256 * it;
            int r = s >> 4, dq = s & 15;
            const float* kp = &g_qkv[(size_t)(t0 + c * 64 + r) * 1536 + 512 + h * 64 + dq * 4];
            float4 v = *(const float4*)kp;
            Ks[(dq * 4 + 0) * 64 + r] = v.x;
            Ks[(dq * 4 + 1) * 64 + r] = v.y;
            Ks[(dq * 4 + 2) * 64 + r] = v.z;
            Ks[(dq * 4 + 3) * 64 + r] = v.w;
            float4 w = *(const float4*)(kp + 512);
            *(float4*)&Vs[r * 64 + dq * 4] = w;
        }
        __syncthreads();

        float s_[4][4];
        #pragma unroll
        for (int i = 0; i < 4; i++)
            #pragma unroll
            for (int j = 0; j < 4; j++) s_[i][j] = 0.f;

        #pragma unroll 8
        for (int d = 0; d < 64; ++d) {
            float4 av = *(const float4*)&Qs[d * 64 + ty * 4];
            float4 bv = *(const float4*)&Ks[d * 64 + tx * 4];
            float a[4] = {av.x, av.y, av.z, av.w};
            float bb[4] = {bv.x, bv.y, bv.z, bv.w};
            #pragma unroll
            for (int i = 0; i < 4; i++)
                #pragma unroll
                for (int j = 0; j < 4; j++)
                    s_[i][j] = fmaf(a[i], bb[j], s_[i][j]);
        }

        float nm[4], alpha[4];
        #pragma unroll
        for (int i = 0; i < 4; i++) {
            float cm = -1e30f;
            #pragma unroll
            for (int j = 0; j < 4; j++) {
                s_[i][j] *= scale;
                cm = fmaxf(cm, s_[i][j]);
            }
            #pragma unroll
            for (int off = 8; off; off >>= 1)
                cm = fmaxf(cm, __shfl_xor_sync(0xffffffffu, cm, off));
            nm[i] = fmaxf(rmax[i], cm);
            alpha[i] = __expf(rmax[i] - nm[i]);
            float cs = 0.f;
            #pragma unroll
            for (int j = 0; j < 4; j++) {
                s_[i][j] = __expf(s_[i][j] - nm[i]);
                cs += s_[i][j];
            }
            #pragma unroll
            for (int off = 8; off; off >>= 1)
                cs += __shfl_xor_sync(0xffffffffu, cs, off);
            rsum[i] = rsum[i] * alpha[i] + cs;
            rmax[i] = nm[i];
            #pragma unroll
            for (int j = 0; j < 4; j++) acc[i][j] *= alpha[i];
        }

        #pragma unroll
        for (int i = 0; i < 4; i++)
            *(float4*)&Ps[(ty * 4 + i) * 64 + tx * 4] =
                make_float4(s_[i][0], s_[i][1], s_[i][2], s_[i][3]);
        __syncthreads();

        #pragma unroll 8
        for (int m = 0; m < 64; ++m) {
            float a[4], bb[4];
            #pragma unroll
            for (int i = 0; i < 4; i++) a[i] = Ps[(ty * 4 + i) * 64 + m];
            float4 bv = *(const float4*)&Vs[m * 64 + tx * 4];
            bb[0]=bv.x; bb[1]=bv.y; bb[2]=bv.z; bb[3]=bv.w;
            #pragma unroll
            for (int i = 0; i < 4; i++)
                #pragma unroll
                for (int j = 0; j < 4; j++)
                    acc[i][j] = fmaf(a[i], bb[j], acc[i][j]);
        }
        __syncthreads();
    }

    #pragma unroll
    for (int i = 0; i < 4; i++) {
        float inv = 1.f / rsum[i];
        float4 v = make_float4(acc[i][0] * inv, acc[i][1] * inv,
                               acc[i][2] * inv, acc[i][3] * inv);
        *(float4*)&g_att[(size_t)(t0 + qrow0 + ty * 4 + i) * CC + h * 64 + tx * 4] = v;
    }
}

// ---------------------------------------------------------------------------
extern "C" void kernel_launch(void* const* d_in, const int* in_sizes, int n_in,
                              void* d_out, int out_size)
{
    const float* x      = (const float*)d_in[0];
    const float* W_qkv  = (const float*)d_in[1];
    const float* W_proj = (const float*)d_in[2];
    const float* b_proj = (const float*)d_in[3];
    float* out = (float*)d_out;

    float* qkv_ptr = nullptr;
    float* att_ptr = nullptr;
    __nv_bfloat16 *wqh, *wql, *wph, *wpl;
    cudaGetSymbolAddress((void**)&qkv_ptr, g_qkv);
    cudaGetSymbolAddress((void**)&att_ptr, g_att);
    cudaGetSymbolAddress((void**)&wqh, g_wq_hi);
    cudaGetSymbolAddress((void**)&wql, g_wq_lo);
    cudaGetSymbolAddress((void**)&wph, g_wp_hi);
    cudaGetSymbolAddress((void**)&wpl, g_wp_lo);

    cudaFuncSetAttribute(gemm_mma_kernel,
                         cudaFuncAttributeMaxDynamicSharedMemorySize, GSM_TOTAL);
    cudaFuncSetAttribute(attn_kernel,
                         cudaFuncAttributeMaxDynamicSharedMemorySize,
                         4 * 64 * 64 * (int)sizeof(float));

    const int M = BB * NN;   // 32768

    // 0) Split weights to bf16 hi/lo (layout [K,N] kept)
    splitw_kernel<<<(3 * CC * CC + 255) / 256, 256>>>(W_qkv, wqh, wql, 3 * CC * CC);
    splitw_kernel<<<(CC * CC + 255) / 256, 256>>>(W_proj, wph, wpl, CC * CC);

    // 1) qkv = x @ W_qkv  (HMMA bf16x3)
    {
        dim3 grid((3 * CC) / 128, M / 128);   // (12, 256)
        gemm_mma_kernel<<<grid, 256, GSM_TOTAL>>>(x, wqh, wql, nullptr, qkv_ptr,
                                                  M, 3 * CC, CC);
    }

    // 2) fused grouped attention
    {
        dim3 grid(LL / 64, BB * GG * HH);
        attn_kernel<<<grid, 256, 4 * 64 * 64 * sizeof(float)>>>();
    }

    // 3) out = att @ W_proj + b_proj  (HMMA bf16x3)
    {
        dim3 grid(CC / 128, M / 128);         // (4, 256)
        gemm_mma_kernel<<<grid, 256, GSM_TOTAL>>>(att_ptr, wph, wpl, b_proj, out,
                                                  M, CC, CC);
    }
}

// round 4
// speedup vs baseline: 1.6790x; 1.1535x over previous
#include <cuda_runtime.h>
#include <cuda_bf16.h>
#include <math.h>
#include <stdint.h>

// Problem constants (recursive_index=0 -> G=8)
#define BB 8
#define NN 4096
#define CC 512
#define GG 8
#define HH 8
#define DH 64
#define LL 512

// Scratch (device globals; no cudaMalloc allowed)
__device__ __nv_bfloat16 g_qkv_hi[(size_t)BB * NN * 3 * CC];  // [32768,1536]
__device__ __nv_bfloat16 g_qkv_lo[(size_t)BB * NN * 3 * CC];
__device__ float g_att[(size_t)BB * NN * CC];                 // [32768,512] fp32
__device__ __nv_bfloat16 g_wq_hi[(size_t)CC * 3 * CC];        // [512,1536] (K,N)
__device__ __nv_bfloat16 g_wq_lo[(size_t)CC * 3 * CC];
__device__ __nv_bfloat16 g_wp_hi[(size_t)CC * CC];
__device__ __nv_bfloat16 g_wp_lo[(size_t)CC * CC];

// ---------------------------------------------------------------------------
// Helpers
// ---------------------------------------------------------------------------
__device__ __forceinline__ uint32_t smem_u32(const void* p) {
    uint32_t a;
    asm("{ .reg .u64 t; cvta.to.shared.u64 t, %1; cvt.u32.u64 %0, t; }" : "=r"(a) : "l"(p));
    return a;
}

#define LDM_X4(r, a) \
    asm volatile("ldmatrix.sync.aligned.m8n8.x4.shared.b16 {%0,%1,%2,%3}, [%4];" \
        : "=r"((r)[0]), "=r"((r)[1]), "=r"((r)[2]), "=r"((r)[3]) : "r"(a))

#define LDM_X4T(r, a) \
    asm volatile("ldmatrix.sync.aligned.m8n8.x4.trans.shared.b16 {%0,%1,%2,%3}, [%4];" \
        : "=r"((r)[0]), "=r"((r)[1]), "=r"((r)[2]), "=r"((r)[3]) : "r"(a))

#define MMA16816(c, a, b0, b1) \
    asm volatile("mma.sync.aligned.m16n8k16.row.col.f32.bf16.bf16.f32 " \
        "{%0,%1,%2,%3}, {%4,%5,%6,%7}, {%8,%9}, {%0,%1,%2,%3};" \
        : "+f"((c)[0]), "+f"((c)[1]), "+f"((c)[2]), "+f"((c)[3]) \
        : "r"((a)[0]), "r"((a)[1]), "r"((a)[2]), "r"((a)[3]), "r"(b0), "r"(b1))

#define CP16(dst, src) \
    asm volatile("cp.async.ca.shared.global [%0], [%1], 16;" :: "r"(dst), "l"(src))
#define CP_COMMIT() asm volatile("cp.async.commit_group;")
#define CP_WAIT0() asm volatile("cp.async.wait_group 0;")
#define CP_WAIT1() asm volatile("cp.async.wait_group 1;")

__device__ __forceinline__ uint32_t pk(__nv_bfloat162 v) {
    return *reinterpret_cast<uint32_t*>(&v);
}
// pack two floats into bf16x2 (hi) and the bf16x2 of remainders (lo)
__device__ __forceinline__ void split2(float a, float b, uint32_t& hi, uint32_t& lo) {
    __nv_bfloat162 h = __floats2bfloat162_rn(a, b);
    __nv_bfloat162 l = __floats2bfloat162_rn(a - __bfloat162float(h.x),
                                             b - __bfloat162float(h.y));
    hi = pk(h); lo = pk(l);
}

// ---------------------------------------------------------------------------
// Split weights: W [K, N] fp32 -> hi/lo [K, N] bf16
// ---------------------------------------------------------------------------
__global__ void splitw_kernel(const float* __restrict__ W,
                              __nv_bfloat16* __restrict__ hi,
                              __nv_bfloat16* __restrict__ lo, int total) {
    int idx = blockIdx.x * blockDim.x + threadIdx.x;
    if (idx >= total) return;
    float v = W[idx];
    __nv_bfloat16 h = __float2bfloat16_rn(v);
    hi[idx] = h;
    lo[idx] = __float2bfloat16_rn(v - __bfloat162float(h));
}

// ---------------------------------------------------------------------------
// HMMA bf16x3 GEMM: C = A(fp32)[M,K] @ B(bf16 hi/lo)[K,N] (+bias)
// Output either fp32 C, or split bf16 (Chi/Clo).
// ---------------------------------------------------------------------------
#define SA 72
#define SB 136
#define SM_AH 0
#define SM_AL (128 * SA * 2)
#define SM_BH (2 * 128 * SA * 2)
#define SM_BL (2 * 128 * SA * 2 + 64 * SB * 2)
#define GSM_TOTAL (2 * 128 * SA * 2 + 2 * 64 * SB * 2)

__global__ __launch_bounds__(256) void gemm_mma_kernel(
    const float* __restrict__ A, const __nv_bfloat16* __restrict__ Bhi,
    const __nv_bfloat16* __restrict__ Blo, const float* __restrict__ bias,
    float* __restrict__ C, __nv_bfloat16* __restrict__ Chi,
    __nv_bfloat16* __restrict__ Clo, int M, int N, int K)
{
    extern __shared__ char sm[];
    const uint32_t sb = smem_u32(sm);
    __nv_bfloat16* Ah = (__nv_bfloat16*)(sm + SM_AH);
    __nv_bfloat16* Al = (__nv_bfloat16*)(sm + SM_AL);
    __nv_bfloat16* Bh = (__nv_bfloat16*)(sm + SM_BH);
    __nv_bfloat16* Bl = (__nv_bfloat16*)(sm + SM_BL);

    const int tid = threadIdx.x;
    const int wid = tid >> 5, lane = tid & 31;
    const int wm = wid >> 2, wn = wid & 3;
    const int gid = lane >> 2, tig = lane & 3;
    const int m0 = blockIdx.y * 128, n0 = blockIdx.x * 128;

    const int a_row = lane & 15;
    const int a_col = (lane >> 4) * 8;
    const int b_krow = lane & 15;
    const int b_ncol = (lane & 16) ? 8 : 0;

    float acc[4][4][4];
    #pragma unroll
    for (int i = 0; i < 4; i++)
        #pragma unroll
        for (int j = 0; j < 4; j++)
            #pragma unroll
            for (int t = 0; t < 4; t++) acc[i][j][t] = 0.f;

    const int NC = K >> 6;
    for (int c = 0; c < NC; ++c) {
        if (c) __syncthreads();
        #pragma unroll
        for (int i = 0; i < 8; ++i) {
            int s = tid + 256 * i;
            int r = s >> 4, q = s & 15;
            float4 v = *(const float4*)&A[(size_t)(m0 + r) * K + c * 64 + q * 4];
            uint32_t h0, l0, h1, l1;
            split2(v.x, v.y, h0, l0);
            split2(v.z, v.w, h1, l1);
            int off = r * SA + q * 4;
            uint2 hh; hh.x = h0; hh.y = h1;
            uint2 ll; ll.x = l0; ll.y = l1;
            *(uint2*)(Ah + off) = hh;
            *(uint2*)(Al + off) = ll;
        }
        #pragma unroll
        for (int i = 0; i < 4; ++i) {
            int s = tid + 256 * i;
            int kr = s >> 4, nq = s & 15;
            size_t g = (size_t)(c * 64 + kr) * N + n0 + nq * 8;
            uint4 vh = *(const uint4*)(Bhi + g);
            uint4 vl = *(const uint4*)(Blo + g);
            int off = kr * SB + nq * 8;
            *(uint4*)(Bh + off) = vh;
            *(uint4*)(Bl + off) = vl;
        }
        __syncthreads();

        #pragma unroll
        for (int ks = 0; ks < 4; ++ks) {
            uint32_t bh[2][4], bl[2][4], af[4][4];
            #pragma unroll
            for (int p = 0; p < 2; ++p) {
                int krow = ks * 16 + b_krow;
                int ncol = wn * 32 + p * 16 + b_ncol;
                LDM_X4T(bh[p], sb + SM_BH + (uint32_t)(krow * SB + ncol) * 2);
                LDM_X4T(bl[p], sb + SM_BL + (uint32_t)(krow * SB + ncol) * 2);
            }
            #pragma unroll
            for (int i = 0; i < 4; ++i) {
                int mr = wm * 64 + i * 16 + a_row;
                LDM_X4(af[i], sb + SM_AH + (uint32_t)(mr * SA + ks * 16 + a_col) * 2);
            }
            #pragma unroll
            for (int i = 0; i < 4; ++i)
                #pragma unroll
                for (int j = 0; j < 4; ++j) {
                    int p = j >> 1, q2 = (j & 1) * 2;
                    MMA16816(acc[i][j], af[i], bh[p][q2], bh[p][q2 + 1]);
                    MMA16816(acc[i][j], af[i], bl[p][q2], bl[p][q2 + 1]);
                }
            #pragma unroll
            for (int i = 0; i < 4; ++i) {
                int mr = wm * 64 + i * 16 + a_row;
                LDM_X4(af[i], sb + SM_AL + (uint32_t)(mr * SA + ks * 16 + a_col) * 2);
            }
            #pragma unroll
            for (int i = 0; i < 4; ++i)
                #pragma unroll
                for (int j = 0; j < 4; ++j) {
                    int p = j >> 1, q2 = (j & 1) * 2;
                    MMA16816(acc[i][j], af[i], bh[p][q2], bh[p][q2 + 1]);
                }
        }
    }

    #pragma unroll
    for (int i = 0; i < 4; ++i) {
        int r0 = m0 + wm * 64 + i * 16 + gid;
        #pragma unroll
        for (int j = 0; j < 4; ++j) {
            int cc = n0 + wn * 32 + j * 8 + 2 * tig;
            float bx = 0.f, by = 0.f;
            if (bias) { bx = bias[cc]; by = bias[cc + 1]; }
            float v0 = acc[i][j][0] + bx, v1 = acc[i][j][1] + by;
            float v2 = acc[i][j][2] + bx, v3 = acc[i][j][3] + by;
            if (Chi) {
                uint32_t h0, l0, h1, l1;
                split2(v0, v1, h0, l0);
                split2(v2, v3, h1, l1);
                *(uint32_t*)&Chi[(size_t)r0 * N + cc] = h0;
                *(uint32_t*)&Clo[(size_t)r0 * N + cc] = l0;
                *(uint32_t*)&Chi[(size_t)(r0 + 8) * N + cc] = h1;
                *(uint32_t*)&Clo[(size_t)(r0 + 8) * N + cc] = l1;
            } else {
                *(float2*)&C[(size_t)r0 * N + cc] = make_float2(v0, v1);
                *(float2*)&C[(size_t)(r0 + 8) * N + cc] = make_float2(v2, v3);
            }
        }
    }
}

// ---------------------------------------------------------------------------
// Tensorized flash attention (HMMA bf16x3).
// CTA: 128 queries x 512 kv (8 chunks of 64). 8 warps x m16 rows.
// Smem: Q hi/lo [128][72], KV double-buffered: K hi/lo + V hi/lo [64][72] each.
// ---------------------------------------------------------------------------
#define AT_QH 0
#define AT_QL 18432
#define AT_KV 36864
#define AT_KVB 36864     // per-buffer stride (KH 0, KL 9216, VH 18432, VL 27648)
#define ATSM_TOTAL (AT_KV + 2 * AT_KVB)   // 110592

__global__ __launch_bounds__(256) void attn_mma_kernel()
{
    extern __shared__ char sm[];
    const uint32_t sb = smem_u32(sm);
    const int tid = threadIdx.x;
    const int w = tid >> 5, lane = tid & 31;
    const int gid = lane >> 2, tig = lane & 3;
    const int bgh = blockIdx.y;
    const int h = bgh & 7;
    const int g = (bgh >> 3) & 7;
    const int b = bgh >> 6;
    const int t0 = b * NN + g * LL;
    const int qrow0 = blockIdx.x * 128;
    const float scale = 0.125f;

    const int a_row = lane & 15;
    const int a_col = (lane >> 4) * 8;
    const int k_nrow = (lane & 7) + ((lane & 16) ? 8 : 0);   // K: [n][k] non-trans
    const int k_kcol = (lane & 8) ? 8 : 0;
    const int v_krow = lane & 15;                             // V: [k][n] trans
    const int v_ncol = (lane & 16) ? 8 : 0;

    // ---- prologue: cp.async Q (hi/lo) + KV chunk 0 ----
    #pragma unroll
    for (int i = 0; i < 4; ++i) {
        int t = tid + 256 * i;
        int r = t >> 3, dq = t & 7;
        size_t go = (size_t)(t0 + qrow0 + r) * 1536 + h * 64 + dq * 8;
        uint32_t d = sb + AT_QH + r * 144 + dq * 16;
        CP16(d, g_qkv_hi + go);
        CP16(d + AT_QL, g_qkv_lo + go);
    }
    #pragma unroll
    for (int i = 0; i < 2; ++i) {
        int t = tid + 256 * i;
        int r = t >> 3, dq = t & 7;
        size_t go = (size_t)(t0 + r) * 1536 + 512 + h * 64 + dq * 8;
        uint32_t d = sb + AT_KV + r * 144 + dq * 16;
        CP16(d, g_qkv_hi + go);
        CP16(d + 9216, g_qkv_lo + go);
        CP16(d + 18432, g_qkv_hi + go + 512);
        CP16(d + 27648, g_qkv_lo + go + 512);
    }
    CP_COMMIT();

    float s_o[8][4];
    float rmax0 = -1e30f, rmax1 = -1e30f, rsum0 = 0.f, rsum1 = 0.f;
    #pragma unroll
    for (int j = 0; j < 8; ++j)
        #pragma unroll
        for (int t = 0; t < 4; ++t) s_o[j][t] = 0.f;

    for (int c = 0; c < 8; ++c) {
        if (c < 7) {
            int buf = (c + 1) & 1;
            #pragma unroll
            for (int i = 0; i < 2; ++i) {
                int t = tid + 256 * i;
                int r = t >> 3, dq = t & 7;
                size_t go = (size_t)(t0 + (c + 1) * 64 + r) * 1536 + 512 + h * 64 + dq * 8;
                uint32_t d = sb + AT_KV + buf * AT_KVB + r * 144 + dq * 16;
                CP16(d, g_qkv_hi + go);
                CP16(d + 9216, g_qkv_lo + go);
                CP16(d + 18432, g_qkv_hi + go + 512);
                CP16(d + 27648, g_qkv_lo + go + 512);
            }
            CP_COMMIT();
            CP_WAIT1();
        } else {
            CP_WAIT0();
        }
        __syncthreads();

        const uint32_t kb = sb + AT_KV + (c & 1) * AT_KVB;        // K hi base
        const uint32_t vb = kb + 18432;                            // V hi base

        // ---- S = scale * Q K^T  (bf16x3) ----
        float s_[8][4];
        #pragma unroll
        for (int j = 0; j < 8; ++j)
            #pragma unroll
            for (int t = 0; t < 4; ++t) s_[j][t] = 0.f;

        #pragma unroll
        for (int ks = 0; ks < 4; ++ks) {
            uint32_t qh[4], ql[4], kh[4][4], kl[4][4];
            uint32_t qa = sb + AT_QH + (uint32_t)((w * 16 + a_row) * 72 + ks * 16 + a_col) * 2;
            LDM_X4(qh, qa);
            LDM_X4(ql, qa + AT_QL);
            #pragma unroll
            for (int p = 0; p < 4; ++p) {
                uint32_t ka = kb + (uint32_t)((p * 16 + k_nrow) * 72 + ks * 16 + k_kcol) * 2;
                LDM_X4(kh[p], ka);
                LDM_X4(kl[p], ka + 9216);
            }
            #pragma unroll
            for (int j = 0; j < 8; ++j) {
                int p = j >> 1, q2 = (j & 1) * 2;
                MMA16816(s_[j], qh, kh[p][q2], kh[p][q2 + 1]);
                MMA16816(s_[j], qh, kl[p][q2], kl[p][q2 + 1]);
                MMA16816(s_[j], ql, kh[p][q2], kh[p][q2 + 1]);
            }
        }

        // ---- online softmax (rows gid and gid+8; stats shared over 4 tig lanes) ----
        float m0 = -1e30f, m1 = -1e30f;
        #pragma unroll
        for (int j = 0; j < 8; ++j) {
            s_[j][0] *= scale; s_[j][1] *= scale;
            s_[j][2] *= scale; s_[j][3] *= scale;
            m0 = fmaxf(m0, fmaxf(s_[j][0], s_[j][1]));
            m1 = fmaxf(m1, fmaxf(s_[j][2], s_[j][3]));
        }
        m0 = fmaxf(m0, __shfl_xor_sync(0xffffffffu, m0, 1));
        m0 = fmaxf(m0, __shfl_xor_sync(0xffffffffu, m0, 2));
        m1 = fmaxf(m1, __shfl_xor_sync(0xffffffffu, m1, 1));
        m1 = fmaxf(m1, __shfl_xor_sync(0xffffffffu, m1, 2));
        float nm0 = fmaxf(rmax0, m0), nm1 = fmaxf(rmax1, m1);
        float al0 = __expf(rmax0 - nm0), al1 = __expf(rmax1 - nm1);
        float cs0 = 0.f, cs1 = 0.f;
        #pragma unroll
        for (int j = 0; j < 8; ++j) {
            s_[j][0] = __expf(s_[j][0] - nm0);
            s_[j][1] = __expf(s_[j][1] - nm0);
            s_[j][2] = __expf(s_[j][2] - nm1);
            s_[j][3] = __expf(s_[j][3] - nm1);
            cs0 += s_[j][0] + s_[j][1];
            cs1 += s_[j][2] + s_[j][3];
        }
        cs0 += __shfl_xor_sync(0xffffffffu, cs0, 1);
        cs0 += __shfl_xor_sync(0xffffffffu, cs0, 2);
        cs1 += __shfl_xor_sync(0xffffffffu, cs1, 1);
        cs1 += __shfl_xor_sync(0xffffffffu, cs1, 2);
        rsum0 = rsum0 * al0 + cs0;
        rsum1 = rsum1 * al1 + cs1;
        rmax0 = nm0; rmax1 = nm1;
        #pragma unroll
        for (int j = 0; j < 8; ++j) {
            s_o[j][0] *= al0; s_o[j][1] *= al0;
            s_o[j][2] *= al1; s_o[j][3] *= al1;
        }

        // ---- O += P @ V (bf16x3; P split in registers) ----
        #pragma unroll
        for (int kf = 0; kf < 4; ++kf) {
            uint32_t ph[4], pl[4], vh[4][4], vl[4][4];
            int ja = 2 * kf, jb = 2 * kf + 1;
            split2(s_[ja][0], s_[ja][1], ph[0], pl[0]);
            split2(s_[ja][2], s_[ja][3], ph[1], pl[1]);
            split2(s_[jb][0], s_[jb][1], ph[2], pl[2]);
            split2(s_[jb][2], s_[jb][3], ph[3], pl[3]);
            #pragma unroll
            for (int p = 0; p < 4; ++p) {
                uint32_t va = vb + (uint32_t)((kf * 16 + v_krow) * 72 + p * 16 + v_ncol) * 2;
                LDM_X4T(vh[p], va);
                LDM_X4T(vl[p], va + 9216);
            }
            #pragma unroll
            for (int j = 0; j < 8; ++j) {
                int p = j >> 1, q2 = (j & 1) * 2;
                MMA16816(s_o[j], ph, vh[p][q2], vh[p][q2 + 1]);
                MMA16816(s_o[j], ph, vl[p][q2], vl[p][q2 + 1]);
                MMA16816(s_o[j], pl, vh[p][q2], vh[p][q2 + 1]);
            }
        }
        __syncthreads();
    }

    // ---- normalize + write g_att [token][512], col = h*64 + d ----
    float inv0 = 1.f / rsum0, inv1 = 1.f / rsum1;
    const int r0 = t0 + qrow0 + w * 16 + gid;
    #pragma unroll
    for (int j = 0; j < 8; ++j) {
        int cc = h * 64 + j * 8 + 2 * tig;
        *(float2*)&g_att[(size_t)r0 * CC + cc] =
            make_float2(s_o[j][0] * inv0, s_o[j][1] * inv0);
        *(float2*)&g_att[(size_t)(r0 + 8) * CC + cc] =
            make_float2(s_o[j][2] * inv1, s_o[j][3] * inv1);
    }
}

// ---------------------------------------------------------------------------
extern "C" void kernel_launch(void* const* d_in, const int* in_sizes, int n_in,
                              void* d_out, int out_size)
{
    const float* x      = (const float*)d_in[0];
    const float* W_qkv  = (const float*)d_in[1];
    const float* W_proj = (const float*)d_in[2];
    const float* b_proj = (const float*)d_in[3];
    float* out = (float*)d_out;

    float* att_ptr = nullptr;
    __nv_bfloat16 *qkvh, *qkvl, *wqh, *wql, *wph, *wpl;
    cudaGetSymbolAddress((void**)&att_ptr, g_att);
    cudaGetSymbolAddress((void**)&qkvh, g_qkv_hi);
    cudaGetSymbolAddress((void**)&qkvl, g_qkv_lo);
    cudaGetSymbolAddress((void**)&wqh, g_wq_hi);
    cudaGetSymbolAddress((void**)&wql, g_wq_lo);
    cudaGetSymbolAddress((void**)&wph, g_wp_hi);
    cudaGetSymbolAddress((void**)&wpl, g_wp_lo);

    cudaFuncSetAttribute(gemm_mma_kernel,
                         cudaFuncAttributeMaxDynamicSharedMemorySize, GSM_TOTAL);
    cudaFuncSetAttribute(attn_mma_kernel,
                         cudaFuncAttributeMaxDynamicSharedMemorySize, ATSM_TOTAL);

    const int M = BB * NN;   // 32768

    // 0) Split weights to bf16 hi/lo
    splitw_kernel<<<(3 * CC * CC + 255) / 256, 256>>>(W_qkv, wqh, wql, 3 * CC * CC);
    splitw_kernel<<<(CC * CC + 255) / 256, 256>>>(W_proj, wph, wpl, CC * CC);

    // 1) qkv = x @ W_qkv  (HMMA bf16x3), output split bf16 hi/lo
    {
        dim3 grid((3 * CC) / 128, M / 128);
        gemm_mma_kernel<<<grid, 256, GSM_TOTAL>>>(x, wqh, wql, nullptr,
                                                  nullptr, qkvh, qkvl,
                                                  M, 3 * CC, CC);
    }

    // 2) tensorized flash attention
    {
        dim3 grid(LL / 128, BB * GG * HH);   // (4, 512)
        attn_mma_kernel<<<grid, 256, ATSM_TOTAL>>>();
    }

    // 3) out = att @ W_proj + b_proj  (HMMA bf16x3), fp32 out
    {
        dim3 grid(CC / 128, M / 128);
        gemm_mma_kernel<<<grid, 256, GSM_TOTAL>>>(att_ptr, wph, wpl, b_proj,
                                                  out, nullptr, nullptr,
                                                  M, CC, CC);
    }
}

// round 5
// speedup vs baseline: 2.4307x; 1.4477x over previous
#include <cuda_runtime.h>
#include <cuda_bf16.h>
#include <math.h>
#include <stdint.h>

// Problem constants (recursive_index=0 -> G=8)
#define BB 8
#define NN 4096
#define CC 512
#define GG 8
#define HH 8
#define DH 64
#define LL 512

// Scratch (device globals; no cudaMalloc allowed)
__device__ __nv_bfloat16 g_qkv_hi[(size_t)BB * NN * 3 * CC];  // [32768,1536]
__device__ __nv_bfloat16 g_qkv_lo[(size_t)BB * NN * 3 * CC];
__device__ float g_att[(size_t)BB * NN * CC];                 // [32768,512] fp32
__device__ __nv_bfloat16 g_wq_hi[(size_t)CC * 3 * CC];        // [512,1536] (K,N)
__device__ __nv_bfloat16 g_wq_lo[(size_t)CC * 3 * CC];
__device__ __nv_bfloat16 g_wp_hi[(size_t)CC * CC];
__device__ __nv_bfloat16 g_wp_lo[(size_t)CC * CC];

// ---------------------------------------------------------------------------
// Helpers
// ---------------------------------------------------------------------------
__device__ __forceinline__ uint32_t smem_u32(const void* p) {
    uint32_t a;
    asm("{ .reg .u64 t; cvta.to.shared.u64 t, %1; cvt.u32.u64 %0, t; }" : "=r"(a) : "l"(p));
    return a;
}

#define LDM_X4(r, a) \
    asm volatile("ldmatrix.sync.aligned.m8n8.x4.shared.b16 {%0,%1,%2,%3}, [%4];" \
        : "=r"((r)[0]), "=r"((r)[1]), "=r"((r)[2]), "=r"((r)[3]) : "r"(a))

#define LDM_X4T(r, a) \
    asm volatile("ldmatrix.sync.aligned.m8n8.x4.trans.shared.b16 {%0,%1,%2,%3}, [%4];" \
        : "=r"((r)[0]), "=r"((r)[1]), "=r"((r)[2]), "=r"((r)[3]) : "r"(a))

#define MMA16816(c, a, b0, b1) \
    asm volatile("mma.sync.aligned.m16n8k16.row.col.f32.bf16.bf16.f32 " \
        "{%0,%1,%2,%3}, {%4,%5,%6,%7}, {%8,%9}, {%0,%1,%2,%3};" \
        : "+f"((c)[0]), "+f"((c)[1]), "+f"((c)[2]), "+f"((c)[3]) \
        : "r"((a)[0]), "r"((a)[1]), "r"((a)[2]), "r"((a)[3]), "r"(b0), "r"(b1))

#define CP16(dst, src) \
    asm volatile("cp.async.ca.shared.global [%0], [%1], 16;" :: "r"(dst), "l"(src))
#define CP_COMMIT() asm volatile("cp.async.commit_group;")
#define CP_WAIT0() asm volatile("cp.async.wait_group 0;")
#define CP_WAIT1() asm volatile("cp.async.wait_group 1;")

__device__ __forceinline__ uint32_t pk(__nv_bfloat162 v) {
    return *reinterpret_cast<uint32_t*>(&v);
}
// pack two floats into bf16x2 (hi) and the bf16x2 of remainders (lo)
__device__ __forceinline__ void split2(float a, float b, uint32_t& hi, uint32_t& lo) {
    __nv_bfloat162 h = __floats2bfloat162_rn(a, b);
    __nv_bfloat162 l = __floats2bfloat162_rn(a - __bfloat162float(h.x),
                                             b - __bfloat162float(h.y));
    hi = pk(h); lo = pk(l);
}

// ---------------------------------------------------------------------------
// Split weights: W [K, N] fp32 -> hi/lo [K, N] bf16
// ---------------------------------------------------------------------------
__global__ void splitw_kernel(const float* __restrict__ W,
                              __nv_bfloat16* __restrict__ hi,
                              __nv_bfloat16* __restrict__ lo, int total) {
    int idx = blockIdx.x * blockDim.x + threadIdx.x;
    if (idx >= total) return;
    float v = W[idx];
    __nv_bfloat16 h = __float2bfloat16_rn(v);
    hi[idx] = h;
    lo[idx] = __float2bfloat16_rn(v - __bfloat162float(h));
}

// ---------------------------------------------------------------------------
// HMMA bf16x3 GEMM: C = A(fp32)[M,K] @ B(bf16 hi/lo)[K,N] (+bias)
// Output either fp32 C, or split bf16 (Chi/Clo).
// ---------------------------------------------------------------------------
#define SA 72
#define SB 136
#define SM_AH 0
#define SM_AL (128 * SA * 2)
#define SM_BH (2 * 128 * SA * 2)
#define SM_BL (2 * 128 * SA * 2 + 64 * SB * 2)
#define GSM_TOTAL (2 * 128 * SA * 2 + 2 * 64 * SB * 2)

__global__ __launch_bounds__(256) void gemm_mma_kernel(
    const float* __restrict__ A, const __nv_bfloat16* __restrict__ Bhi,
    const __nv_bfloat16* __restrict__ Blo, const float* __restrict__ bias,
    float* __restrict__ C, __nv_bfloat16* __restrict__ Chi,
    __nv_bfloat16* __restrict__ Clo, int M, int N, int K)
{
    extern __shared__ char sm[];
    const uint32_t sb = smem_u32(sm);
    __nv_bfloat16* Ah = (__nv_bfloat16*)(sm + SM_AH);
    __nv_bfloat16* Al = (__nv_bfloat16*)(sm + SM_AL);
    __nv_bfloat16* Bh = (__nv_bfloat16*)(sm + SM_BH);
    __nv_bfloat16* Bl = (__nv_bfloat16*)(sm + SM_BL);

    const int tid = threadIdx.x;
    const int wid = tid >> 5, lane = tid & 31;
    const int wm = wid >> 2, wn = wid & 3;
    const int gid = lane >> 2, tig = lane & 3;
    const int m0 = blockIdx.y * 128, n0 = blockIdx.x * 128;

    const int a_row = lane & 15;
    const int a_col = (lane >> 4) * 8;
    const int b_krow = lane & 15;
    const int b_ncol = (lane & 16) ? 8 : 0;

    float acc[4][4][4];
    #pragma unroll
    for (int i = 0; i < 4; i++)
        #pragma unroll
        for (int j = 0; j < 4; j++)
            #pragma unroll
            for (int t = 0; t < 4; t++) acc[i][j][t] = 0.f;

    const int NC = K >> 6;
    for (int c = 0; c < NC; ++c) {
        if (c) __syncthreads();
        #pragma unroll
        for (int i = 0; i < 8; ++i) {
            int s = tid + 256 * i;
            int r = s >> 4, q = s & 15;
            float4 v = *(const float4*)&A[(size_t)(m0 + r) * K + c * 64 + q * 4];
            uint32_t h0, l0, h1, l1;
            split2(v.x, v.y, h0, l0);
            split2(v.z, v.w, h1, l1);
            int off = r * SA + q * 4;
            uint2 hh; hh.x = h0; hh.y = h1;
            uint2 ll; ll.x = l0; ll.y = l1;
            *(uint2*)(Ah + off) = hh;
            *(uint2*)(Al + off) = ll;
        }
        #pragma unroll
        for (int i = 0; i < 4; ++i) {
            int s = tid + 256 * i;
            int kr = s >> 4, nq = s & 15;
            size_t g = (size_t)(c * 64 + kr) * N + n0 + nq * 8;
            uint4 vh = *(const uint4*)(Bhi + g);
            uint4 vl = *(const uint4*)(Blo + g);
            int off = kr * SB + nq * 8;
            *(uint4*)(Bh + off) = vh;
            *(uint4*)(Bl + off) = vl;
        }
        __syncthreads();

        #pragma unroll
        for (int ks = 0; ks < 4; ++ks) {
            uint32_t bh[2][4], bl[2][4], af[4][4];
            #pragma unroll
            for (int p = 0; p < 2; ++p) {
                int krow = ks * 16 + b_krow;
                int ncol = wn * 32 + p * 16 + b_ncol;
                LDM_X4T(bh[p], sb + SM_BH + (uint32_t)(krow * SB + ncol) * 2);
                LDM_X4T(bl[p], sb + SM_BL + (uint32_t)(krow * SB + ncol) * 2);
            }
            #pragma unroll
            for (int i = 0; i < 4; ++i) {
                int mr = wm * 64 + i * 16 + a_row;
                LDM_X4(af[i], sb + SM_AH + (uint32_t)(mr * SA + ks * 16 + a_col) * 2);
            }
            #pragma unroll
            for (int i = 0; i < 4; ++i)
                #pragma unroll
                for (int j = 0; j < 4; ++j) {
                    int p = j >> 1, q2 = (j & 1) * 2;
                    MMA16816(acc[i][j], af[i], bh[p][q2], bh[p][q2 + 1]);
                    MMA16816(acc[i][j], af[i], bl[p][q2], bl[p][q2 + 1]);
                }
            #pragma unroll
            for (int i = 0; i < 4; ++i) {
                int mr = wm * 64 + i * 16 + a_row;
                LDM_X4(af[i], sb + SM_AL + (uint32_t)(mr * SA + ks * 16 + a_col) * 2);
            }
            #pragma unroll
            for (int i = 0; i < 4; ++i)
                #pragma unroll
                for (int j = 0; j < 4; ++j) {
                    int p = j >> 1, q2 = (j & 1) * 2;
                    MMA16816(acc[i][j], af[i], bh[p][q2], bh[p][q2 + 1]);
                }
        }
    }

    #pragma unroll
    for (int i = 0; i < 4; ++i) {
        int r0 = m0 + wm * 64 + i * 16 + gid;
        #pragma unroll
        for (int j = 0; j < 4; ++j) {
            int cc = n0 + wn * 32 + j * 8 + 2 * tig;
            float bx = 0.f, by = 0.f;
            if (bias) { bx = bias[cc]; by = bias[cc + 1]; }
            float v0 = acc[i][j][0] + bx, v1 = acc[i][j][1] + by;
            float v2 = acc[i][j][2] + bx, v3 = acc[i][j][3] + by;
            if (Chi) {
                uint32_t h0, l0, h1, l1;
                split2(v0, v1, h0, l0);
                split2(v2, v3, h1, l1);
                *(uint32_t*)&Chi[(size_t)r0 * N + cc] = h0;
                *(uint32_t*)&Clo[(size_t)r0 * N + cc] = l0;
                *(uint32_t*)&Chi[(size_t)(r0 + 8) * N + cc] = h1;
                *(uint32_t*)&Clo[(size_t)(r0 + 8) * N + cc] = l1;
            } else {
                *(float2*)&C[(size_t)r0 * N + cc] = make_float2(v0, v1);
                *(float2*)&C[(size_t)(r0 + 8) * N + cc] = make_float2(v2, v3);
            }
        }
    }
}

// ---------------------------------------------------------------------------
// Tensorized flash attention (HMMA bf16x3).
// CTA: 128 queries x 512 kv (8 chunks of 64). 8 warps x m16 rows.
// Smem: Q hi/lo [128][72], KV double-buffered: K hi/lo + V hi/lo [64][72] each.
// ---------------------------------------------------------------------------
#define AT_QH 0
#define AT_QL 18432
#define AT_KV 36864
#define AT_KVB 36864     // per-buffer stride (KH 0, KL 9216, VH 18432, VL 27648)
#define ATSM_TOTAL (AT_KV + 2 * AT_KVB)   // 110592

__global__ __launch_bounds__(256) void attn_mma_kernel()
{
    extern __shared__ char sm[];
    const uint32_t sb = smem_u32(sm);
    const int tid = threadIdx.x;
    const int w = tid >> 5, lane = tid & 31;
    const int gid = lane >> 2, tig = lane & 3;
    const int bgh = blockIdx.y;
    const int h = bgh & 7;
    const int g = (bgh >> 3) & 7;
    const int b = bgh >> 6;
    const int t0 = b * NN + g * LL;
    const int qrow0 = blockIdx.x * 128;
    const float scale = 0.125f;

    const int a_row = lane & 15;
    const int a_col = (lane >> 4) * 8;
    const int k_nrow = (lane & 7) + ((lane & 16) ? 8 : 0);   // K: [n][k] non-trans
    const int k_kcol = (lane & 8) ? 8 : 0;
    const int v_krow = lane & 15;                             // V: [k][n] trans
    const int v_ncol = (lane & 16) ? 8 : 0;

    // ---- prologue: cp.async Q (hi/lo) + KV chunk 0 ----
    #pragma unroll
    for (int i = 0; i < 4; ++i) {
        int t = tid + 256 * i;
        int r = t >> 3, dq = t & 7;
        size_t go = (size_t)(t0 + qrow0 + r) * 1536 + h * 64 + dq * 8;
        uint32_t d = sb + AT_QH + r * 144 + dq * 16;
        CP16(d, g_qkv_hi + go);
        CP16(d + AT_QL, g_qkv_lo + go);
    }
    #pragma unroll
    for (int i = 0; i < 2; ++i) {
        int t = tid + 256 * i;
        int r = t >> 3, dq = t & 7;
        size_t go = (size_t)(t0 + r) * 1536 + 512 + h * 64 + dq * 8;
        uint32_t d = sb + AT_KV + r * 144 + dq * 16;
        CP16(d, g_qkv_hi + go);
        CP16(d + 9216, g_qkv_lo + go);
        CP16(d + 18432, g_qkv_hi + go + 512);
        CP16(d + 27648, g_qkv_lo + go + 512);
    }
    CP_COMMIT();

    float s_o[8][4];
    float rmax0 = -1e30f, rmax1 = -1e30f, rsum0 = 0.f, rsum1 = 0.f;
    #pragma unroll
    for (int j = 0; j < 8; ++j)
        #pragma unroll
        for (int t = 0; t < 4; ++t) s_o[j][t] = 0.f;

    for (int c = 0; c < 8; ++c) {
        if (c < 7) {
            int buf = (c + 1) & 1;
            #pragma unroll
            for (int i = 0; i < 2; ++i) {
                int t = tid + 256 * i;
                int r = t >> 3, dq = t & 7;
                size_t go = (size_t)(t0 + (c + 1) * 64 + r) * 1536 + 512 + h * 64 + dq * 8;
                uint32_t d = sb + AT_KV + buf * AT_KVB + r * 144 + dq * 16;
                CP16(d, g_qkv_hi + go);
                CP16(d + 9216, g_qkv_lo + go);
                CP16(d + 18432, g_qkv_hi + go + 512);
                CP16(d + 27648, g_qkv_lo + go + 512);
            }
            CP_COMMIT();
            CP_WAIT1();
        } else {
            CP_WAIT0();
        }
        __syncthreads();

        const uint32_t kb = sb + AT_KV + (c & 1) * AT_KVB;        // K hi base
        const uint32_t vb = kb + 18432;                            // V hi base

        // ---- S = scale * Q K^T  (bf16x3) ----
        float s_[8][4];
        #pragma unroll
        for (int j = 0; j < 8; ++j)
            #pragma unroll
            for (int t = 0; t < 4; ++t) s_[j][t] = 0.f;

        #pragma unroll
        for (int ks = 0; ks < 4; ++ks) {
            uint32_t qh[4], ql[4], kh[4][4], kl[4][4];
            uint32_t qa = sb + AT_QH + (uint32_t)((w * 16 + a_row) * 72 + ks * 16 + a_col) * 2;
            LDM_X4(qh, qa);
            LDM_X4(ql, qa + AT_QL);
            #pragma unroll
            for (int p = 0; p < 4; ++p) {
                uint32_t ka = kb + (uint32_t)((p * 16 + k_nrow) * 72 + ks * 16 + k_kcol) * 2;
                LDM_X4(kh[p], ka);
                LDM_X4(kl[p], ka + 9216);
            }
            #pragma unroll
            for (int j = 0; j < 8; ++j) {
                int p = j >> 1, q2 = (j & 1) * 2;
                MMA16816(s_[j], qh, kh[p][q2], kh[p][q2 + 1]);
                MMA16816(s_[j], qh, kl[p][q2], kl[p][q2 + 1]);
                MMA16816(s_[j], ql, kh[p][q2], kh[p][q2 + 1]);
            }
        }

        // ---- online softmax (rows gid and gid+8; stats shared over 4 tig lanes) ----
        float m0 = -1e30f, m1 = -1e30f;
        #pragma unroll
        for (int j = 0; j < 8; ++j) {
            s_[j][0] *= scale; s_[j][1] *= scale;
            s_[j][2] *= scale; s_[j][3] *= scale;
            m0 = fmaxf(m0, fmaxf(s_[j][0], s_[j][1]));
            m1 = fmaxf(m1, fmaxf(s_[j][2], s_[j][3]));
        }
        m0 = fmaxf(m0, __shfl_xor_sync(0xffffffffu, m0, 1));
        m0 = fmaxf(m0, __shfl_xor_sync(0xffffffffu, m0, 2));
        m1 = fmaxf(m1, __shfl_xor_sync(0xffffffffu, m1, 1));
        m1 = fmaxf(m1, __shfl_xor_sync(0xffffffffu, m1, 2));
        float nm0 = fmaxf(rmax0, m0), nm1 = fmaxf(rmax1, m1);
        float al0 = __expf(rmax0 - nm0), al1 = __expf(rmax1 - nm1);
        float cs0 = 0.f, cs1 = 0.f;
        #pragma unroll
        for (int j = 0; j < 8; ++j) {
            s_[j][0] = __expf(s_[j][0] - nm0);
            s_[j][1] = __expf(s_[j][1] - nm0);
            s_[j][2] = __expf(s_[j][2] - nm1);
            s_[j][3] = __expf(s_[j][3] - nm1);
            cs0 += s_[j][0] + s_[j][1];
            cs1 += s_[j][2] + s_[j][3];
        }
        cs0 += __shfl_xor_sync(0xffffffffu, cs0, 1);
        cs0 += __shfl_xor_sync(0xffffffffu, cs0, 2);
        cs1 += __shfl_xor_sync(0xffffffffu, cs1, 1);
        cs1 += __shfl_xor_sync(0xffffffffu, cs1, 2);
        rsum0 = rsum0 * al0 + cs0;
        rsum1 = rsum1 * al1 + cs1;
        rmax0 = nm0; rmax1 = nm1;
        #pragma unroll
        for (int j = 0; j < 8; ++j) {
            s_o[j][0] *= al0; s_o[j][1] *= al0;
            s_o[j][2] *= al1; s_o[j][3] *= al1;
        }

        // ---- O += P @ V (bf16x3; P split in registers) ----
        #pragma unroll
        for (int kf = 0; kf < 4; ++kf) {
            uint32_t ph[4], pl[4], vh[4][4], vl[4][4];
            int ja = 2 * kf, jb = 2 * kf + 1;
            split2(s_[ja][0], s_[ja][1], ph[0], pl[0]);
            split2(s_[ja][2], s_[ja][3], ph[1], pl[1]);
            split2(s_[jb][0], s_[jb][1], ph[2], pl[2]);
            split2(s_[jb][2], s_[jb][3], ph[3], pl[3]);
            #pragma unroll
            for (int p = 0; p < 4; ++p) {
                uint32_t va = vb + (uint32_t)((kf * 16 + v_krow) * 72 + p * 16 + v_ncol) * 2;
                LDM_X4T(vh[p], va);
                LDM_X4T(vl[p], va + 9216);
            }
            #pragma unroll
            for (int j = 0; j < 8; ++j) {
                int p = j >> 1, q2 = (j & 1) * 2;
                MMA16816(s_o[j], ph, vh[p][q2], vh[p][q2 + 1]);
                MMA16816(s_o[j], ph, vl[p][q2], vl[p][q2 + 1]);
                MMA16816(s_o[j], pl, vh[p][q2], vh[p][q2 + 1]);
            }
        }
        __syncthreads();
    }

    // ---- normalize + write g_att [token][512], col = h*64 + d ----
    float inv0 = 1.f / rsum0, inv1 = 1.f / rsum1;
    const int r0 = t0 + qrow0 + w * 16 + gid;
    #pragma unroll
    for (int j = 0; j < 8; ++j) {
        int cc = h * 64 + j * 8 + 2 * tig;
        *(float2*)&g_att[(size_t)r0 * CC + cc] =
            make_float2(s_o[j][0] * inv0, s_o[j][1] * inv0);
        *(float2*)&g_att[(size_t)(r0 + 8) * CC + cc] =
            make_float2(s_o[j][2] * inv1, s_o[j][3] * inv1);
    }
}

// ---------------------------------------------------------------------------
extern "C" void kernel_launch(void* const* d_in, const int* in_sizes, int n_in,
                              void* d_out, int out_size)
{
    const float* x      = (const float*)d_in[0];
    const float* W_qkv  = (const float*)d_in[1];
    const float* W_proj = (const float*)d_in[2];
    const float* b_proj = (const float*)d_in[3];
    float* out = (float*)d_out;

    float* att_ptr = nullptr;
    __nv_bfloat16 *qkvh, *qkvl, *wqh, *wql, *wph, *wpl;
    cudaGetSymbolAddress((void**)&att_ptr, g_att);
    cudaGetSymbolAddress((void**)&qkvh, g_qkv_hi);
    cudaGetSymbolAddress((void**)&qkvl, g_qkv_lo);
    cudaGetSymbolAddress((void**)&wqh, g_wq_hi);
    cudaGetSymbolAddress((void**)&wql, g_wq_lo);
    cudaGetSymbolAddress((void**)&wph, g_wp_hi);
    cudaGetSymbolAddress((void**)&wpl, g_wp_lo);

    cudaFuncSetAttribute(gemm_mma_kernel,
                         cudaFuncAttributeMaxDynamicSharedMemorySize, GSM_TOTAL);
    cudaFuncSetAttribute(attn_mma_kernel,
                         cudaFuncAttributeMaxDynamicSharedMemorySize, ATSM_TOTAL);

    const int M = BB * NN;   // 32768

    // 0) Split weights to bf16 hi/lo
    splitw_kernel<<<(3 * CC * CC + 255) / 256, 256>>>(W_qkv, wqh, wql, 3 * CC * CC);
    splitw_kernel<<<(CC * CC + 255) / 256, 256>>>(W_proj, wph, wpl, CC * CC);

    // 1) qkv = x @ W_qkv  (HMMA bf16x3), output split bf16 hi/lo
    {
        dim3 grid((3 * CC) / 128, M / 128);
        gemm_mma_kernel<<<grid, 256, GSM_TOTAL>>>(x, wqh, wql, nullptr,
                                                  nullptr, qkvh, qkvl,
                                                  M, 3 * CC, CC);
    }

    // 2) tensorized flash attention
    {
        dim3 grid(LL / 128, BB * GG * HH);   // (4, 512)
        attn_mma_kernel<<<grid, 256, ATSM_TOTAL>>>();
    }

    // 3) out = att @ W_proj + b_proj  (HMMA bf16x3), fp32 out
    {
        dim3 grid(CC / 128, M / 128);
        gemm_mma_kernel<<<grid, 256, GSM_TOTAL>>>(att_ptr, wph, wpl, b_proj,
                                                  out, nullptr, nullptr,
                                                  M, CC, CC);
    }
}

// round 6
// speedup vs baseline: 2.9986x; 1.2336x over previous
#include <cuda_runtime.h>
#include <cuda_bf16.h>
#include <math.h>
#include <stdint.h>

// Problem constants (recursive_index=0 -> G=8)
#define BB 8
#define NN 4096
#define CC 512
#define GG 8
#define HH 8
#define DH 64
#define LL 512

// Scratch (device globals; no cudaMalloc allowed)
__device__ __nv_bfloat16 g_x_hi[(size_t)BB * NN * CC];        // [32768,512]
__device__ __nv_bfloat16 g_x_lo[(size_t)BB * NN * CC];
__device__ __nv_bfloat16 g_qkv_hi[(size_t)BB * NN * 3 * CC];  // [32768,1536]
__device__ __nv_bfloat16 g_qkv_lo[(size_t)BB * NN * 3 * CC];
__device__ __nv_bfloat16 g_att_hi[(size_t)BB * NN * CC];      // [32768,512]
__device__ __nv_bfloat16 g_att_lo[(size_t)BB * NN * CC];
__device__ __nv_bfloat16 g_wq_hi[(size_t)CC * 3 * CC];        // [512,1536] (K,N)
__device__ __nv_bfloat16 g_wq_lo[(size_t)CC * 3 * CC];
__device__ __nv_bfloat16 g_wp_hi[(size_t)CC * CC];
__device__ __nv_bfloat16 g_wp_lo[(size_t)CC * CC];

// ---------------------------------------------------------------------------
// Helpers
// ---------------------------------------------------------------------------
__device__ __forceinline__ uint32_t smem_u32(const void* p) {
    uint32_t a;
    asm("{ .reg .u64 t; cvta.to.shared.u64 t, %1; cvt.u32.u64 %0, t; }" : "=r"(a) : "l"(p));
    return a;
}

#define LDM_X4(r, a) \
    asm volatile("ldmatrix.sync.aligned.m8n8.x4.shared.b16 {%0,%1,%2,%3}, [%4];" \
        : "=r"((r)[0]), "=r"((r)[1]), "=r"((r)[2]), "=r"((r)[3]) : "r"(a))

#define LDM_X4T(r, a) \
    asm volatile("ldmatrix.sync.aligned.m8n8.x4.trans.shared.b16 {%0,%1,%2,%3}, [%4];" \
        : "=r"((r)[0]), "=r"((r)[1]), "=r"((r)[2]), "=r"((r)[3]) : "r"(a))

#define MMA16816(c, a, b0, b1) \
    asm volatile("mma.sync.aligned.m16n8k16.row.col.f32.bf16.bf16.f32 " \
        "{%0,%1,%2,%3}, {%4,%5,%6,%7}, {%8,%9}, {%0,%1,%2,%3};" \
        : "+f"((c)[0]), "+f"((c)[1]), "+f"((c)[2]), "+f"((c)[3]) \
        : "r"((a)[0]), "r"((a)[1]), "r"((a)[2]), "r"((a)[3]), "r"(b0), "r"(b1))

#define CP16(dst, src) \
    asm volatile("cp.async.ca.shared.global [%0], [%1], 16;" :: "r"(dst), "l"(src))
#define CP_COMMIT() asm volatile("cp.async.commit_group;")
#define CP_WAIT0() asm volatile("cp.async.wait_group 0;")
#define CP_WAIT1() asm volatile("cp.async.wait_group 1;")

__device__ __forceinline__ uint32_t pk(__nv_bfloat162 v) {
    return *reinterpret_cast<uint32_t*>(&v);
}
__device__ __forceinline__ void split2(float a, float b, uint32_t& hi, uint32_t& lo) {
    __nv_bfloat162 h = __floats2bfloat162_rn(a, b);
    __nv_bfloat162 l = __floats2bfloat162_rn(a - __bfloat162float(h.x),
                                             b - __bfloat162float(h.y));
    hi = pk(h); lo = pk(l);
}

// ---------------------------------------------------------------------------
// Split fp32 -> bf16 hi/lo (weights and x)
// ---------------------------------------------------------------------------
__global__ void splitw_kernel(const float* __restrict__ W,
                              __nv_bfloat16* __restrict__ hi,
                              __nv_bfloat16* __restrict__ lo, int total) {
    int idx = blockIdx.x * blockDim.x + threadIdx.x;
    if (idx >= total) return;
    float v = W[idx];
    __nv_bfloat16 h = __float2bfloat16_rn(v);
    hi[idx] = h;
    lo[idx] = __float2bfloat16_rn(v - __bfloat162float(h));
}

__global__ void splitx_kernel(const float* __restrict__ X,
                              __nv_bfloat16* __restrict__ hi,
                              __nv_bfloat16* __restrict__ lo) {
    int idx = blockIdx.x * blockDim.x + threadIdx.x;   // float4 index
    float4 v = *(const float4*)(X + (size_t)idx * 4);
    uint32_t h0, l0, h1, l1;
    split2(v.x, v.y, h0, l0);
    split2(v.z, v.w, h1, l1);
    uint2 hh; hh.x = h0; hh.y = h1;
    uint2 ll; ll.x = l0; ll.y = l1;
    *(uint2*)(hi + (size_t)idx * 4) = hh;
    *(uint2*)(lo + (size_t)idx * 4) = ll;
}

// ---------------------------------------------------------------------------
// All-bf16 HMMA x3 GEMM, cp.async 2-stage pipeline.
// C[M,N] = (Ah+Al)[M,K] @ (Bh+Bl)[K,N] (3-term), + bias.
// CTA 128x128, BK=32, 8 warps (2x4 of 64x32), 2 CTAs/SM.
// Stage layout (bytes, bf16 strides: A row 40, B row 136):
//   Ah 0..10240, Al 10240..20480, Bh 20480..29184, Bl 29184..37888
// ---------------------------------------------------------------------------
#define PSA 40
#define PSB 136
#define PS_AL 10240
#define PS_BH 20480
#define PS_BL 29184
#define PSS   37888
#define PGSM_TOTAL (2 * PSS)

__global__ __launch_bounds__(256, 2) void gemm_bf3_kernel(
    const __nv_bfloat16* __restrict__ Ahi, const __nv_bfloat16* __restrict__ Alo,
    const __nv_bfloat16* __restrict__ Bhi, const __nv_bfloat16* __restrict__ Blo,
    const float* __restrict__ bias, float* __restrict__ C,
    __nv_bfloat16* __restrict__ Chi, __nv_bfloat16* __restrict__ Clo,
    int M, int N, int K)
{
    extern __shared__ char sm[];
    const uint32_t sb = smem_u32(sm);
    const int tid = threadIdx.x;
    const int wid = tid >> 5, lane = tid & 31;
    const int wm = wid >> 2, wn = wid & 3;
    const int gid = lane >> 2, tig = lane & 3;
    const int m0 = blockIdx.y * 128, n0 = blockIdx.x * 128;

    const int a_row = lane & 15;
    const int a_col = (lane >> 4) * 8;
    const int b_krow = lane & 15;
    const int b_ncol = (lane & 16) ? 8 : 0;

    // cp.async mapping (per stage, per split: A 512x16B, B 512x16B)
    const int ar = tid >> 2, aq = tid & 3;          // +256 -> ar+64
    const int br = tid >> 4, bq = tid & 15;         // +256 -> br+16

    auto load_stage = [&](int c, int buf) {
        const uint32_t s0 = sb + buf * PSS;
        const int k0 = c * 32;
        #pragma unroll
        for (int i = 0; i < 2; ++i) {
            int r = ar + 64 * i;
            size_t ga = (size_t)(m0 + r) * K + k0 + aq * 8;
            uint32_t d = s0 + r * (PSA * 2) + aq * 16;
            CP16(d, Ahi + ga);
            CP16(d + PS_AL, Alo + ga);
        }
        #pragma unroll
        for (int i = 0; i < 2; ++i) {
            int r = br + 16 * i;
            size_t gb = (size_t)(k0 + r) * N + n0 + bq * 8;
            uint32_t d = s0 + PS_BH + r * (PSB * 2) + bq * 16;
            CP16(d, Bhi + gb);
            CP16(d + (PS_BL - PS_BH), Blo + gb);
        }
        CP_COMMIT();
    };

    float acc[4][4][4];
    #pragma unroll
    for (int i = 0; i < 4; i++)
        #pragma unroll
        for (int j = 0; j < 4; j++)
            #pragma unroll
            for (int t = 0; t < 4; t++) acc[i][j][t] = 0.f;

    const int NC = K >> 5;   // 32-wide chunks
    load_stage(0, 0);

    for (int c = 0; c < NC; ++c) {
        if (c + 1 < NC) { load_stage(c + 1, (c + 1) & 1); CP_WAIT1(); }
        else            { CP_WAIT0(); }
        __syncthreads();

        const uint32_t s0 = sb + (c & 1) * PSS;
        #pragma unroll
        for (int ks = 0; ks < 2; ++ks) {
            uint32_t bh[2][4], bl[2][4], af[4][4];
            #pragma unroll
            for (int p = 0; p < 2; ++p) {
                uint32_t ba = s0 + PS_BH
                    + (uint32_t)((ks * 16 + b_krow) * PSB + wn * 32 + p * 16 + b_ncol) * 2;
                LDM_X4T(bh[p], ba);
                LDM_X4T(bl[p], ba + (PS_BL - PS_BH));
            }
            #pragma unroll
            for (int i = 0; i < 4; ++i) {
                uint32_t aa = s0
                    + (uint32_t)((wm * 64 + i * 16 + a_row) * PSA + ks * 16 + a_col) * 2;
                LDM_X4(af[i], aa);
            }
            #pragma unroll
            for (int i = 0; i < 4; ++i)
                #pragma unroll
                for (int j = 0; j < 4; ++j) {
                    int p = j >> 1, q2 = (j & 1) * 2;
                    MMA16816(acc[i][j], af[i], bh[p][q2], bh[p][q2 + 1]);
                    MMA16816(acc[i][j], af[i], bl[p][q2], bl[p][q2 + 1]);
                }
            #pragma unroll
            for (int i = 0; i < 4; ++i) {
                uint32_t aa = s0 + PS_AL
                    + (uint32_t)((wm * 64 + i * 16 + a_row) * PSA + ks * 16 + a_col) * 2;
                LDM_X4(af[i], aa);
            }
            #pragma unroll
            for (int i = 0; i < 4; ++i)
                #pragma unroll
                for (int j = 0; j < 4; ++j) {
                    int p = j >> 1, q2 = (j & 1) * 2;
                    MMA16816(acc[i][j], af[i], bh[p][q2], bh[p][q2 + 1]);
                }
        }
        __syncthreads();   // protect buffer reuse by next iteration's cp.async
    }

    #pragma unroll
    for (int i = 0; i < 4; ++i) {
        int r0 = m0 + wm * 64 + i * 16 + gid;
        #pragma unroll
        for (int j = 0; j < 4; ++j) {
            int cc = n0 + wn * 32 + j * 8 + 2 * tig;
            float bx = 0.f, by = 0.f;
            if (bias) { bx = bias[cc]; by = bias[cc + 1]; }
            float v0 = acc[i][j][0] + bx, v1 = acc[i][j][1] + by;
            float v2 = acc[i][j][2] + bx, v3 = acc[i][j][3] + by;
            if (Chi) {
                uint32_t h0, l0, h1, l1;
                split2(v0, v1, h0, l0);
                split2(v2, v3, h1, l1);
                *(uint32_t*)&Chi[(size_t)r0 * N + cc] = h0;
                *(uint32_t*)&Clo[(size_t)r0 * N + cc] = l0;
                *(uint32_t*)&Chi[(size_t)(r0 + 8) * N + cc] = h1;
                *(uint32_t*)&Clo[(size_t)(r0 + 8) * N + cc] = l1;
            } else {
                *(float2*)&C[(size_t)r0 * N + cc] = make_float2(v0, v1);
                *(float2*)&C[(size_t)(r0 + 8) * N + cc] = make_float2(v2, v3);
            }
        }
    }
}

// ---------------------------------------------------------------------------
// Tensorized flash attention (HMMA bf16x3). Epilogue now writes bf16 hi/lo.
// ---------------------------------------------------------------------------
#define AT_QH 0
#define AT_QL 18432
#define AT_KV 36864
#define AT_KVB 36864
#define ATSM_TOTAL (AT_KV + 2 * AT_KVB)   // 110592

__global__ __launch_bounds__(256) void attn_mma_kernel()
{
    extern __shared__ char sm[];
    const uint32_t sb = smem_u32(sm);
    const int tid = threadIdx.x;
    const int w = tid >> 5, lane = tid & 31;
    const int gid = lane >> 2, tig = lane & 3;
    const int bgh = blockIdx.y;
    const int h = bgh & 7;
    const int g = (bgh >> 3) & 7;
    const int b = bgh >> 6;
    const int t0 = b * NN + g * LL;
    const int qrow0 = blockIdx.x * 128;
    const float scale = 0.125f;

    const int a_row = lane & 15;
    const int a_col = (lane >> 4) * 8;
    const int k_nrow = (lane & 7) + ((lane & 16) ? 8 : 0);
    const int k_kcol = (lane & 8) ? 8 : 0;
    const int v_krow = lane & 15;
    const int v_ncol = (lane & 16) ? 8 : 0;

    #pragma unroll
    for (int i = 0; i < 4; ++i) {
        int t = tid + 256 * i;
        int r = t >> 3, dq = t & 7;
        size_t go = (size_t)(t0 + qrow0 + r) * 1536 + h * 64 + dq * 8;
        uint32_t d = sb + AT_QH + r * 144 + dq * 16;
        CP16(d, g_qkv_hi + go);
        CP16(d + AT_QL, g_qkv_lo + go);
    }
    #pragma unroll
    for (int i = 0; i < 2; ++i) {
        int t = tid + 256 * i;
        int r = t >> 3, dq = t & 7;
        size_t go = (size_t)(t0 + r) * 1536 + 512 + h * 64 + dq * 8;
        uint32_t d = sb + AT_KV + r * 144 + dq * 16;
        CP16(d, g_qkv_hi + go);
        CP16(d + 9216, g_qkv_lo + go);
        CP16(d + 18432, g_qkv_hi + go + 512);
        CP16(d + 27648, g_qkv_lo + go + 512);
    }
    CP_COMMIT();

    float s_o[8][4];
    float rmax0 = -1e30f, rmax1 = -1e30f, rsum0 = 0.f, rsum1 = 0.f;
    #pragma unroll
    for (int j = 0; j < 8; ++j)
        #pragma unroll
        for (int t = 0; t < 4; ++t) s_o[j][t] = 0.f;

    for (int c = 0; c < 8; ++c) {
        if (c < 7) {
            int buf = (c + 1) & 1;
            #pragma unroll
            for (int i = 0; i < 2; ++i) {
                int t = tid + 256 * i;
                int r = t >> 3, dq = t & 7;
                size_t go = (size_t)(t0 + (c + 1) * 64 + r) * 1536 + 512 + h * 64 + dq * 8;
                uint32_t d = sb + AT_KV + buf * AT_KVB + r * 144 + dq * 16;
                CP16(d, g_qkv_hi + go);
                CP16(d + 9216, g_qkv_lo + go);
                CP16(d + 18432, g_qkv_hi + go + 512);
                CP16(d + 27648, g_qkv_lo + go + 512);
            }
            CP_COMMIT();
            CP_WAIT1();
        } else {
            CP_WAIT0();
        }
        __syncthreads();

        const uint32_t kb = sb + AT_KV + (c & 1) * AT_KVB;
        const uint32_t vb = kb + 18432;

        float s_[8][4];
        #pragma unroll
        for (int j = 0; j < 8; ++j)
            #pragma unroll
            for (int t = 0; t < 4; ++t) s_[j][t] = 0.f;

        #pragma unroll
        for (int ks = 0; ks < 4; ++ks) {
            uint32_t qh[4], ql[4], kh[4][4], kl[4][4];
            uint32_t qa = sb + AT_QH + (uint32_t)((w * 16 + a_row) * 72 + ks * 16 + a_col) * 2;
            LDM_X4(qh, qa);
            LDM_X4(ql, qa + AT_QL);
            #pragma unroll
            for (int p = 0; p < 4; ++p) {
                uint32_t ka = kb + (uint32_t)((p * 16 + k_nrow) * 72 + ks * 16 + k_kcol) * 2;
                LDM_X4(kh[p], ka);
                LDM_X4(kl[p], ka + 9216);
            }
            #pragma unroll
            for (int j = 0; j < 8; ++j) {
                int p = j >> 1, q2 = (j & 1) * 2;
                MMA16816(s_[j], qh, kh[p][q2], kh[p][q2 + 1]);
                MMA16816(s_[j], qh, kl[p][q2], kl[p][q2 + 1]);
                MMA16816(s_[j], ql, kh[p][q2], kh[p][q2 + 1]);
            }
        }

        float m0 = -1e30f, m1 = -1e30f;
        #pragma unroll
        for (int j = 0; j < 8; ++j) {
            s_[j][0] *= scale; s_[j][1] *= scale;
            s_[j][2] *= scale; s_[j][3] *= scale;
            m0 = fmaxf(m0, fmaxf(s_[j][0], s_[j][1]));
            m1 = fmaxf(m1, fmaxf(s_[j][2], s_[j][3]));
        }
        m0 = fmaxf(m0, __shfl_xor_sync(0xffffffffu, m0, 1));
        m0 = fmaxf(m0, __shfl_xor_sync(0xffffffffu, m0, 2));
        m1 = fmaxf(m1, __shfl_xor_sync(0xffffffffu, m1, 1));
        m1 = fmaxf(m1, __shfl_xor_sync(0xffffffffu, m1, 2));
        float nm0 = fmaxf(rmax0, m0), nm1 = fmaxf(rmax1, m1);
        float al0 = __expf(rmax0 - nm0), al1 = __expf(rmax1 - nm1);
        float cs0 = 0.f, cs1 = 0.f;
        #pragma unroll
        for (int j = 0; j < 8; ++j) {
            s_[j][0] = __expf(s_[j][0] - nm0);
            s_[j][1] = __expf(s_[j][1] - nm0);
            s_[j][2] = __expf(s_[j][2] - nm1);
            s_[j][3] = __expf(s_[j][3] - nm1);
            cs0 += s_[j][0] + s_[j][1];
            cs1 += s_[j][2] + s_[j][3];
        }
        cs0 += __shfl_xor_sync(0xffffffffu, cs0, 1);
        cs0 += __shfl_xor_sync(0xffffffffu, cs0, 2);
        cs1 += __shfl_xor_sync(0xffffffffu, cs1, 1);
        cs1 += __shfl_xor_sync(0xffffffffu, cs1, 2);
        rsum0 = rsum0 * al0 + cs0;
        rsum1 = rsum1 * al1 + cs1;
        rmax0 = nm0; rmax1 = nm1;
        #pragma unroll
        for (int j = 0; j < 8; ++j) {
            s_o[j][0] *= al0; s_o[j][1] *= al0;
            s_o[j][2] *= al1; s_o[j][3] *= al1;
        }

        #pragma unroll
        for (int kf = 0; kf < 4; ++kf) {
            uint32_t ph[4], pl[4], vh[4][4], vl[4][4];
            int ja = 2 * kf, jb = 2 * kf + 1;
            split2(s_[ja][0], s_[ja][1], ph[0], pl[0]);
            split2(s_[ja][2], s_[ja][3], ph[1], pl[1]);
            split2(s_[jb][0], s_[jb][1], ph[2], pl[2]);
            split2(s_[jb][2], s_[jb][3], ph[3], pl[3]);
            #pragma unroll
            for (int p = 0; p < 4; ++p) {
                uint32_t va = vb + (uint32_t)((kf * 16 + v_krow) * 72 + p * 16 + v_ncol) * 2;
                LDM_X4T(vh[p], va);
                LDM_X4T(vl[p], va + 9216);
            }
            #pragma unroll
            for (int j = 0; j < 8; ++j) {
                int p = j >> 1, q2 = (j & 1) * 2;
                MMA16816(s_o[j], ph, vh[p][q2], vh[p][q2 + 1]);
                MMA16816(s_o[j], ph, vl[p][q2], vl[p][q2 + 1]);
                MMA16816(s_o[j], pl, vh[p][q2], vh[p][q2 + 1]);
            }
        }
        __syncthreads();
    }

    // ---- normalize + write split bf16 hi/lo, [token][512], col = h*64 + d ----
    float inv0 = 1.f / rsum0, inv1 = 1.f / rsum1;
    const int r0 = t0 + qrow0 + w * 16 + gid;
    #pragma unroll
    for (int j = 0; j < 8; ++j) {
        int cc = h * 64 + j * 8 + 2 * tig;
        uint32_t h0, l0, h1, l1;
        split2(s_o[j][0] * inv0, s_o[j][1] * inv0, h0, l0);
        split2(s_o[j][2] * inv1, s_o[j][3] * inv1, h1, l1);
        *(uint32_t*)&g_att_hi[(size_t)r0 * CC + cc] = h0;
        *(uint32_t*)&g_att_lo[(size_t)r0 * CC + cc] = l0;
        *(uint32_t*)&g_att_hi[(size_t)(r0 + 8) * CC + cc] = h1;
        *(uint32_t*)&g_att_lo[(size_t)(r0 + 8) * CC + cc] = l1;
    }
}

// ---------------------------------------------------------------------------
extern "C" void kernel_launch(void* const* d_in, const int* in_sizes, int n_in,
                              void* d_out, int out_size)
{
    const float* x      = (const float*)d_in[0];
    const float* W_qkv  = (const float*)d_in[1];
    const float* W_proj = (const float*)d_in[2];
    const float* b_proj = (const float*)d_in[3];
    float* out = (float*)d_out;

    __nv_bfloat16 *xh, *xl, *qkvh, *qkvl, *ath, *atl, *wqh, *wql, *wph, *wpl;
    cudaGetSymbolAddress((void**)&xh, g_x_hi);
    cudaGetSymbolAddress((void**)&xl, g_x_lo);
    cudaGetSymbolAddress((void**)&qkvh, g_qkv_hi);
    cudaGetSymbolAddress((void**)&qkvl, g_qkv_lo);
    cudaGetSymbolAddress((void**)&ath, g_att_hi);
    cudaGetSymbolAddress((void**)&atl, g_att_lo);
    cudaGetSymbolAddress((void**)&wqh, g_wq_hi);
    cudaGetSymbolAddress((void**)&wql, g_wq_lo);
    cudaGetSymbolAddress((void**)&wph, g_wp_hi);
    cudaGetSymbolAddress((void**)&wpl, g_wp_lo);

    cudaFuncSetAttribute(gemm_bf3_kernel,
                         cudaFuncAttributeMaxDynamicSharedMemorySize, PGSM_TOTAL);
    cudaFuncSetAttribute(attn_mma_kernel,
                         cudaFuncAttributeMaxDynamicSharedMemorySize, ATSM_TOTAL);

    const int M = BB * NN;   // 32768

    // 0) Splits
    splitw_kernel<<<(3 * CC * CC + 255) / 256, 256>>>(W_qkv, wqh, wql, 3 * CC * CC);
    splitw_kernel<<<(CC * CC + 255) / 256, 256>>>(W_proj, wph, wpl, CC * CC);
    splitx_kernel<<<(M * CC / 4) / 256, 256>>>(x, xh, xl);

    // 1) qkv = x @ W_qkv  (bf16x3, pipelined), split bf16 out
    {
        dim3 grid((3 * CC) / 128, M / 128);
        gemm_bf3_kernel<<<grid, 256, PGSM_TOTAL>>>(xh, xl, wqh, wql, nullptr,
                                                   nullptr, qkvh, qkvl,
                                                   M, 3 * CC, CC);
    }

    // 2) tensorized flash attention -> split bf16 out
    {
        dim3 grid(LL / 128, BB * GG * HH);
        attn_mma_kernel<<<grid, 256, ATSM_TOTAL>>>();
    }

    // 3) out = att @ W_proj + b_proj  (bf16x3, pipelined), fp32 out
    {
        dim3 grid(CC / 128, M / 128);
        gemm_bf3_kernel<<<grid, 256, PGSM_TOTAL>>>(ath, atl, wph, wpl, b_proj,
                                                   out, nullptr, nullptr,
                                                   M, CC, CC);
    }
}